// round 1
// baseline (speedup 1.0000x reference)
#include <cuda_runtime.h>
#include <math.h>

// Problem constants (fixed by reference)
#define NMAX   50000
#define C      128        // IN_C == HID
#define LIN    256
#define NCLS   10
#define NGRAPH 512

// ---------------- scratch (no allocation allowed) ----------------
__device__ float g_H [NMAX * C];   // X @ W
__device__ float g_A1[NMAX * C];   // aggregation / layer output ping
__device__ float g_A2[NMAX * C];   // aggregation / layer output pong
__device__ float g_deg [NMAX];
__device__ float g_dinv[NMAX];
__device__ float g_pooled[NGRAPH * C];
__device__ int   g_flags[2];       // [0]: edge_index is int64, [1]: batch is int64

__device__ __forceinline__ long idx_at(const void* p, long i, int is64) {
    if (is64) return (long)((const long long*)p)[i];
    return (long)((const int*)p)[i];
}

// ---------------- init: flags=1, deg=0, zero d_out ----------------
__global__ void k_init(float* out, long out_n) {
    long t = blockIdx.x * (long)blockDim.x + threadIdx.x;
    long stride = gridDim.x * (long)blockDim.x;
    if (t == 0) { g_flags[0] = 1; g_flags[1] = 1; }
    for (long i = t; i < NMAX; i += stride) g_deg[i] = 0.f;
    for (long i = t; i < out_n; i += stride) out[i] = 0.f;
}

// ---------------- dtype detection -------------------------------
// Scan the buffers as 32-bit words (word count = element count, a safe lower
// bound for both widths). If ANY odd-position word is nonzero, data cannot be
// little-endian int64 of small nonnegative ints -> int32.
__global__ void k_detect(const unsigned* ew, long ewords,
                         const unsigned* bw, long bwords) {
    long t = blockIdx.x * (long)blockDim.x + threadIdx.x;
    long stride = gridDim.x * (long)blockDim.x;
    int bad_e = 0, bad_b = 0;
    for (long i = t; 2 * i + 1 < ewords; i += stride) bad_e |= (ew[2 * i + 1] != 0u);
    for (long i = t; 2 * i + 1 < bwords; i += stride) bad_b |= (bw[2 * i + 1] != 0u);
    if (bad_e) g_flags[0] = 0;
    if (bad_b) g_flags[1] = 0;
}

// ---------------- degree over col (+1 self-loop later) -----------
__global__ void k_deg(const void* ei, long E) {
    long e = blockIdx.x * (long)blockDim.x + threadIdx.x;
    if (e >= E) return;
    int is64 = g_flags[0];
    long c = idx_at(ei, E + e, is64);
    atomicAdd(&g_deg[c], 1.0f);
}

__global__ void k_dinv(int n) {
    int i = blockIdx.x * blockDim.x + threadIdx.x;
    if (i < n) g_dinv[i] = rsqrtf(g_deg[i] + 1.0f);   // +1: self-loop
}

// ---------------- zero an aggregation buffer ---------------------
__global__ void k_zero(float* A, long n4) {   // n4 = count of float4
    long t = blockIdx.x * (long)blockDim.x + threadIdx.x;
    long stride = gridDim.x * (long)blockDim.x;
    float4 z = make_float4(0.f, 0.f, 0.f, 0.f);
    for (long i = t; i < n4; i += stride) ((float4*)A)[i] = z;
}

// ---------------- GEMM: H[M,128] = X[M,128] @ W[128,128] ---------
// Block: 256 threads, 32 rows x 128 cols, 4x4 register tile per thread.
// K split into 4 tiles of 32. X-values are warp-uniform SMEM broadcasts.
__global__ void k_gemm(const float* __restrict__ X, const float* __restrict__ W,
                       float* __restrict__ H, int M) {
    __shared__ float ws[32 * 128];
    __shared__ float xs[32 * 32];
    const int tid = threadIdx.x;
    const int m0  = blockIdx.x * 32;
    const int rg  = tid >> 5;      // 0..7 : rows rg*4..rg*4+3
    const int cg  = tid & 31;      // 0..31: cols cg*4..cg*4+3
    const int lrow = tid >> 3;     // 0..31 (x-tile loader)
    const int lk   = (tid & 7) * 4;

    float acc[4][4];
#pragma unroll
    for (int i = 0; i < 4; ++i)
#pragma unroll
        for (int j = 0; j < 4; ++j) acc[i][j] = 0.f;

    for (int kt = 0; kt < 4; ++kt) {
        // load W k-slice [32][128] (rows kt*32..): contiguous copy
#pragma unroll
        for (int j = 0; j < 4; ++j) {
            int off = tid * 4 + j * 1024;
            *(float4*)&ws[off] = *(const float4*)&W[kt * 32 * 128 + off];
        }
        // load X tile [32 rows][32 k]
        {
            int grow = m0 + lrow;
            float4 xv = make_float4(0.f, 0.f, 0.f, 0.f);
            if (grow < M) xv = *(const float4*)&X[(long)grow * C + kt * 32 + lk];
            *(float4*)&xs[lrow * 32 + lk] = xv;
        }
        __syncthreads();
#pragma unroll
        for (int k = 0; k < 32; ++k) {
            float4 wv = *(const float4*)&ws[k * 128 + cg * 4];
            float a0 = xs[(rg * 4 + 0) * 32 + k];
            float a1 = xs[(rg * 4 + 1) * 32 + k];
            float a2 = xs[(rg * 4 + 2) * 32 + k];
            float a3 = xs[(rg * 4 + 3) * 32 + k];
            acc[0][0] += a0 * wv.x; acc[0][1] += a0 * wv.y; acc[0][2] += a0 * wv.z; acc[0][3] += a0 * wv.w;
            acc[1][0] += a1 * wv.x; acc[1][1] += a1 * wv.y; acc[1][2] += a1 * wv.z; acc[1][3] += a1 * wv.w;
            acc[2][0] += a2 * wv.x; acc[2][1] += a2 * wv.y; acc[2][2] += a2 * wv.z; acc[2][3] += a2 * wv.w;
            acc[3][0] += a3 * wv.x; acc[3][1] += a3 * wv.y; acc[3][2] += a3 * wv.z; acc[3][3] += a3 * wv.w;
        }
        __syncthreads();
    }
#pragma unroll
    for (int i = 0; i < 4; ++i) {
        int row = m0 + rg * 4 + i;
        if (row < M) {
            float4 o = make_float4(acc[i][0], acc[i][1], acc[i][2], acc[i][3]);
            *(float4*)&H[(long)row * C + cg * 4] = o;
        }
    }
}

// ---------------- edge scatter: A[col] += dinv[r]*dinv[c] * H[row] ----
// One warp per edge; lane handles 4 channels via float4; vector red (sm_90+).
__global__ void k_scatter(const float* __restrict__ H, float* __restrict__ A,
                          const void* ei, long E) {
    long t = blockIdx.x * (long)blockDim.x + threadIdx.x;
    long e = t >> 5;
    if (e >= E) return;
    const int lane = threadIdx.x & 31;
    const int is64 = g_flags[0];
    long r = idx_at(ei, e, is64);
    long c = idx_at(ei, E + e, is64);
    float w = g_dinv[r] * g_dinv[c];
    float4 h = *(const float4*)(H + r * (long)C + lane * 4);
    float4 v = make_float4(h.x * w, h.y * w, h.z * w, h.w * w);
    float* p = A + c * (long)C + lane * 4;
    asm volatile("red.global.add.v4.f32 [%0], {%1,%2,%3,%4};"
                 :: "l"(p), "f"(v.x), "f"(v.y), "f"(v.z), "f"(v.w) : "memory");
}

// ---------------- epilogue: X = relu(A + dinv^2 * H + b) (in place over A) ----
__global__ void k_epilogue(float* __restrict__ A, const float* __restrict__ H,
                           const float* __restrict__ b, int M) {
    long idx = blockIdx.x * (long)blockDim.x + threadIdx.x;   // float4 index
    long n4 = (long)M * (C / 4);
    if (idx >= n4) return;
    long n  = idx >> 5;          // node
    int  c4 = (int)(idx & 31);   // float4 within row
    float s = g_dinv[n]; s = s * s;
    float4 a = ((float4*)A)[idx];
    float4 h = ((const float4*)H)[idx];
    float4 bb = ((const float4*)b)[c4];
    float4 o;
    o.x = fmaxf(a.x + s * h.x + bb.x, 0.f);
    o.y = fmaxf(a.y + s * h.y + bb.y, 0.f);
    o.z = fmaxf(a.z + s * h.z + bb.z, 0.f);
    o.w = fmaxf(a.w + s * h.w + bb.w, 0.f);
    ((float4*)A)[idx] = o;
}

// ---------------- mean pool per graph (batch is sorted) ----------
__global__ void k_pool(const float* __restrict__ X, const void* batch, int N) {
    int g = blockIdx.x;
    int c = threadIdx.x;
    int is64 = g_flags[1];
    // lower bounds via binary search
    long a = 0, b = N;
    while (a < b) { long m = (a + b) >> 1; if (idx_at(batch, m, is64) < (long)g) a = m + 1; else b = m; }
    long lo = a;
    a = lo; b = N;
    while (a < b) { long m = (a + b) >> 1; if (idx_at(batch, m, is64) < (long)g + 1) a = m + 1; else b = m; }
    long hi = a;
    float s = 0.f;
    for (long i = lo; i < hi; ++i) s += X[i * (long)C + c];
    long cnt = hi - lo; if (cnt < 1) cnt = 1;
    g_pooled[g * C + c] = s / (float)cnt;
}

// ---------------- MLP + log_softmax -----------------------------
__global__ void k_mlp(const float* __restrict__ w1, const float* __restrict__ b1,
                      const float* __restrict__ w2, const float* __restrict__ b2,
                      float* __restrict__ out, long out_n) {
    __shared__ float p[C];
    __shared__ float z1[LIN];
    __shared__ float lg[NCLS];
    int g = blockIdx.x;
    int t = threadIdx.x;
    if (t < C) p[t] = g_pooled[g * C + t];
    __syncthreads();
    float acc = b1[t];
#pragma unroll 8
    for (int k = 0; k < C; ++k) acc += p[k] * w1[k * LIN + t];
    z1[t] = fmaxf(acc, 0.f);
    __syncthreads();
    if (t < NCLS) {
        float a = b2[t];
#pragma unroll 8
        for (int k = 0; k < LIN; ++k) a += z1[k] * w2[k * NCLS + t];
        lg[t] = a;
    }
    __syncthreads();
    if (t == 0) {
        float m = lg[0];
        for (int j = 1; j < NCLS; ++j) m = fmaxf(m, lg[j]);
        float s = 0.f;
        for (int j = 0; j < NCLS; ++j) s += expf(lg[j] - m);
        float lse = m + logf(s);
        for (int j = 0; j < NCLS; ++j) {
            long o = (long)g * NCLS + j;
            if (o < out_n) out[o] = lg[j] - lse;
        }
    }
}

// ---------------- launch ----------------------------------------
extern "C" void kernel_launch(void* const* d_in, const int* in_sizes, int n_in,
                              void* d_out, int out_size) {
    const float* x    = (const float*)d_in[0];
    const void*  ei   = d_in[1];
    const void*  bat  = d_in[2];
    const float* W1   = (const float*)d_in[3];
    const float* b1   = (const float*)d_in[4];
    const float* W2   = (const float*)d_in[5];
    const float* b2   = (const float*)d_in[6];
    const float* W3   = (const float*)d_in[7];
    const float* b3   = (const float*)d_in[8];
    const float* l1w  = (const float*)d_in[9];
    const float* l1b  = (const float*)d_in[10];
    const float* l2w  = (const float*)d_in[11];
    const float* l2b  = (const float*)d_in[12];
    float* out = (float*)d_out;

    const int  M = in_sizes[0] / C;          // 50000 nodes
    const long E = (long)in_sizes[1] / 2;    // 1.6M edges
    const int  N = in_sizes[2];              // == M

    // resolve scratch symbol addresses (pure queries; capture-safe)
    float *H, *A1, *A2;
    cudaGetSymbolAddress((void**)&H,  g_H);
    cudaGetSymbolAddress((void**)&A1, g_A1);
    cudaGetSymbolAddress((void**)&A2, g_A2);

    const long nelem = (long)M * C;
    const long n4    = nelem / 4;

    k_init<<<256, 256>>>(out, (long)out_size);
    k_detect<<<1024, 256>>>((const unsigned*)ei, (long)in_sizes[1],
                            (const unsigned*)bat, (long)in_sizes[2]);
    k_deg<<<(int)((E + 255) / 256), 256>>>(ei, E);
    k_dinv<<<(M + 255) / 256, 256>>>(M);

    const int gemm_blocks = (M + 31) / 32;
    const int scat_blocks = (int)((E * 32 + 255) / 256);
    const int epi_blocks  = (int)((n4 + 255) / 256);

    // Layer 1: x -> A1
    k_gemm<<<gemm_blocks, 256>>>(x, W1, H, M);
    k_zero<<<1024, 256>>>(A1, n4);
    k_scatter<<<scat_blocks, 256>>>(H, A1, ei, E);
    k_epilogue<<<epi_blocks, 256>>>(A1, H, b1, M);

    // Layer 2: A1 -> A2
    k_gemm<<<gemm_blocks, 256>>>(A1, W2, H, M);
    k_zero<<<1024, 256>>>(A2, n4);
    k_scatter<<<scat_blocks, 256>>>(H, A2, ei, E);
    k_epilogue<<<epi_blocks, 256>>>(A2, H, b2, M);

    // Layer 3: A2 -> A1
    k_gemm<<<gemm_blocks, 256>>>(A2, W3, H, M);
    k_zero<<<1024, 256>>>(A1, n4);
    k_scatter<<<scat_blocks, 256>>>(H, A1, ei, E);
    k_epilogue<<<epi_blocks, 256>>>(A1, H, b3, M);

    // Pool + MLP
    k_pool<<<NGRAPH, C>>>(A1, bat, N);
    k_mlp<<<NGRAPH, LIN>>>(l1w, l1b, l2w, l2b, out, (long)out_size);
}

// round 3
// speedup vs baseline: 1.6922x; 1.6922x over previous
#include <cuda_runtime.h>
#include <math.h>

// Problem constants (fixed by reference)
#define NMAX   50000
#define EMAX   1600000
#define C      128        // IN_C == HID
#define LIN    256
#define NCLS   10
#define NGRAPH 512

// ---------------- scratch (no allocation allowed) ----------------
__device__ float g_H [NMAX * C];    // X @ W
__device__ float g_A1[NMAX * C];    // layer output ping
__device__ float g_A2[NMAX * C];    // layer output pong
__device__ int   g_degi[NMAX];
__device__ float g_dinv[NMAX];
__device__ int   g_off [NMAX + 1];  // CSR offsets (by dst)
__device__ int   g_cur [NMAX];      // fill cursors
struct Edge { int src; float w; };
__device__ Edge  g_e   [EMAX];      // CSR payload: (src, weight)
__device__ float g_pooled[NGRAPH * C];
__device__ int   g_flags[2];        // [0]: edge_index is int64, [1]: batch is int64

__device__ __forceinline__ long idx_at(const void* p, long i, int is64) {
    if (is64) return (long)((const long long*)p)[i];
    return (long)((const int*)p)[i];
}

// ---------------- init: flags=1, deg=0, zero d_out ----------------
__global__ void k_init(float* out, long out_n) {
    long t = blockIdx.x * (long)blockDim.x + threadIdx.x;
    long stride = gridDim.x * (long)blockDim.x;
    if (t == 0) { g_flags[0] = 1; g_flags[1] = 1; }
    for (long i = t; i < NMAX; i += stride) g_degi[i] = 0;
    for (long i = t; i < out_n; i += stride) out[i] = 0.f;
}

// ---------------- dtype detection --------------------------------
// Scan buffers as 32-bit words. If ANY odd-position word is nonzero, data
// cannot be little-endian int64 of small nonneg ints -> int32.
__global__ void k_detect(const unsigned* ew, long ewords,
                         const unsigned* bw, long bwords) {
    long t = blockIdx.x * (long)blockDim.x + threadIdx.x;
    long stride = gridDim.x * (long)blockDim.x;
    int bad_e = 0, bad_b = 0;
    for (long i = t; 2 * i + 1 < ewords; i += stride) bad_e |= (ew[2 * i + 1] != 0u);
    for (long i = t; 2 * i + 1 < bwords; i += stride) bad_b |= (bw[2 * i + 1] != 0u);
    if (bad_e) g_flags[0] = 0;
    if (bad_b) g_flags[1] = 0;
}

// ---------------- in-degree over col -----------------------------
__global__ void k_deg(const void* ei, long E) {
    long e = blockIdx.x * (long)blockDim.x + threadIdx.x;
    if (e >= E) return;
    int is64 = g_flags[0];
    long c = idx_at(ei, E + e, is64);
    atomicAdd(&g_degi[c], 1);
}

__global__ void k_dinv(int n) {
    int i = blockIdx.x * blockDim.x + threadIdx.x;
    if (i < n) g_dinv[i] = rsqrtf((float)g_degi[i] + 1.0f);   // +1: self-loop
}

// ---------------- exclusive scan of degrees (single block) --------
__global__ void k_scan(int n) {
    __shared__ int sums[1024];
    const int t = threadIdx.x;
    const int per = (n + 1023) / 1024;
    const int lo = t * per;
    const int hi = min(lo + per, n);
    int s = 0;
    for (int i = lo; i < hi; ++i) s += g_degi[i];
    sums[t] = s;
    __syncthreads();
    for (int d = 1; d < 1024; d <<= 1) {
        int v = 0;
        if (t >= d) v = sums[t - d];
        __syncthreads();
        if (t >= d) sums[t] += v;
        __syncthreads();
    }
    int run = (t == 0) ? 0 : sums[t - 1];
    for (int i = lo; i < hi; ++i) {
        g_off[i] = run;
        g_cur[i] = run;
        run += g_degi[i];
    }
    if (t == 1023) g_off[n] = sums[1023];
}

// ---------------- CSR fill (counting-sort by dst) -----------------
__global__ void k_fill(const void* ei, long E) {
    long e = blockIdx.x * (long)blockDim.x + threadIdx.x;
    if (e >= E) return;
    int is64 = g_flags[0];
    int r = (int)idx_at(ei, e, is64);
    int c = (int)idx_at(ei, E + e, is64);
    int pos = atomicAdd(&g_cur[c], 1);
    Edge ed; ed.src = r; ed.w = g_dinv[r] * g_dinv[c];
    g_e[pos] = ed;
}

// ---------------- GEMM: H[M,128] = X[M,128] @ W[128,128] ---------
// 256 threads: 32 rows x 128 cols, 4x4 register tile per thread.
__global__ void k_gemm(const float* __restrict__ X, const float* __restrict__ W,
                       float* __restrict__ H, int M) {
    __shared__ float ws[32 * 128];
    __shared__ float xs[32 * 32];
    const int tid = threadIdx.x;
    const int m0  = blockIdx.x * 32;
    const int rg  = tid >> 5;
    const int cg  = tid & 31;
    const int lrow = tid >> 3;
    const int lk   = (tid & 7) * 4;

    float acc[4][4];
#pragma unroll
    for (int i = 0; i < 4; ++i)
#pragma unroll
        for (int j = 0; j < 4; ++j) acc[i][j] = 0.f;

    for (int kt = 0; kt < 4; ++kt) {
#pragma unroll
        for (int j = 0; j < 4; ++j) {
            int off = tid * 4 + j * 1024;
            *(float4*)&ws[off] = *(const float4*)&W[kt * 32 * 128 + off];
        }
        {
            int grow = m0 + lrow;
            float4 xv = make_float4(0.f, 0.f, 0.f, 0.f);
            if (grow < M) xv = *(const float4*)&X[(long)grow * C + kt * 32 + lk];
            *(float4*)&xs[lrow * 32 + lk] = xv;
        }
        __syncthreads();
#pragma unroll
        for (int k = 0; k < 32; ++k) {
            float4 wv = *(const float4*)&ws[k * 128 + cg * 4];
            float a0 = xs[(rg * 4 + 0) * 32 + k];
            float a1 = xs[(rg * 4 + 1) * 32 + k];
            float a2 = xs[(rg * 4 + 2) * 32 + k];
            float a3 = xs[(rg * 4 + 3) * 32 + k];
            acc[0][0] += a0 * wv.x; acc[0][1] += a0 * wv.y; acc[0][2] += a0 * wv.z; acc[0][3] += a0 * wv.w;
            acc[1][0] += a1 * wv.x; acc[1][1] += a1 * wv.y; acc[1][2] += a1 * wv.z; acc[1][3] += a1 * wv.w;
            acc[2][0] += a2 * wv.x; acc[2][1] += a2 * wv.y; acc[2][2] += a2 * wv.z; acc[2][3] += a2 * wv.w;
            acc[3][0] += a3 * wv.x; acc[3][1] += a3 * wv.y; acc[3][2] += a3 * wv.z; acc[3][3] += a3 * wv.w;
        }
        __syncthreads();
    }
#pragma unroll
    for (int i = 0; i < 4; ++i) {
        int row = m0 + rg * 4 + i;
        if (row < M) {
            float4 o = make_float4(acc[i][0], acc[i][1], acc[i][2], acc[i][3]);
            *(float4*)&H[(long)row * C + cg * 4] = o;
        }
    }
}

// ---------------- gather-aggregate + self-loop + bias + relu ------
// One warp per destination node. Lane l owns channels [4l, 4l+4).
// Edge (src,w) pairs are read warp-uniformly (L1 broadcast, one LDG.64/edge).
// A[n] = relu( sum_e w_e * H[src_e]  +  dinv[n]^2 * H[n]  +  b )
__global__ void k_gather(const float* __restrict__ H, float* __restrict__ A,
                         const float* __restrict__ bias, int M) {
    const int warp = (int)((blockIdx.x * (long)blockDim.x + threadIdx.x) >> 5);
    if (warp >= M) return;
    const int lane = threadIdx.x & 31;
    const int n = warp;
    const int beg = g_off[n];
    const int end = g_off[n + 1];

    float s = g_dinv[n]; s = s * s;
    float4 h = __ldg((const float4*)(H + (long)n * C) + lane);
    float4 acc = make_float4(s * h.x, s * h.y, s * h.z, s * h.w);

    int j = beg;
    for (; j + 4 <= end; j += 4) {
        Edge e0 = g_e[j + 0];
        Edge e1 = g_e[j + 1];
        Edge e2 = g_e[j + 2];
        Edge e3 = g_e[j + 3];
        float4 a = __ldg((const float4*)(H + (long)e0.src * C) + lane);
        float4 b = __ldg((const float4*)(H + (long)e1.src * C) + lane);
        float4 c = __ldg((const float4*)(H + (long)e2.src * C) + lane);
        float4 d = __ldg((const float4*)(H + (long)e3.src * C) + lane);
        acc.x += e0.w * a.x; acc.y += e0.w * a.y; acc.z += e0.w * a.z; acc.w += e0.w * a.w;
        acc.x += e1.w * b.x; acc.y += e1.w * b.y; acc.z += e1.w * b.z; acc.w += e1.w * b.w;
        acc.x += e2.w * c.x; acc.y += e2.w * c.y; acc.z += e2.w * c.z; acc.w += e2.w * c.w;
        acc.x += e3.w * d.x; acc.y += e3.w * d.y; acc.z += e3.w * d.z; acc.w += e3.w * d.w;
    }
    for (; j < end; ++j) {
        Edge e = g_e[j];
        float4 a = __ldg((const float4*)(H + (long)e.src * C) + lane);
        acc.x += e.w * a.x; acc.y += e.w * a.y; acc.z += e.w * a.z; acc.w += e.w * a.w;
    }

    float4 bb = __ldg((const float4*)bias + lane);
    acc.x = fmaxf(acc.x + bb.x, 0.f);
    acc.y = fmaxf(acc.y + bb.y, 0.f);
    acc.z = fmaxf(acc.z + bb.z, 0.f);
    acc.w = fmaxf(acc.w + bb.w, 0.f);
    ((float4*)(A + (long)n * C))[lane] = acc;
}

// ---------------- mean pool per graph (batch is sorted) ----------
__global__ void k_pool(const float* __restrict__ X, const void* batch, int N) {
    int g = blockIdx.x;
    int c = threadIdx.x;
    int is64 = g_flags[1];
    long a = 0, b = N;
    while (a < b) { long m = (a + b) >> 1; if (idx_at(batch, m, is64) < (long)g) a = m + 1; else b = m; }
    long lo = a;
    a = lo; b = N;
    while (a < b) { long m = (a + b) >> 1; if (idx_at(batch, m, is64) < (long)g + 1) a = m + 1; else b = m; }
    long hi = a;
    float s = 0.f;
    for (long i = lo; i < hi; ++i) s += X[i * (long)C + c];
    long cnt = hi - lo; if (cnt < 1) cnt = 1;
    g_pooled[g * C + c] = s / (float)cnt;
}

// ---------------- MLP + log_softmax -----------------------------
__global__ void k_mlp(const float* __restrict__ w1, const float* __restrict__ b1,
                      const float* __restrict__ w2, const float* __restrict__ b2,
                      float* __restrict__ out, long out_n) {
    __shared__ float p[C];
    __shared__ float z1[LIN];
    __shared__ float lg[NCLS];
    int g = blockIdx.x;
    int t = threadIdx.x;
    if (t < C) p[t] = g_pooled[g * C + t];
    __syncthreads();
    float acc = b1[t];
#pragma unroll 8
    for (int k = 0; k < C; ++k) acc += p[k] * w1[k * LIN + t];
    z1[t] = fmaxf(acc, 0.f);
    __syncthreads();
    if (t < NCLS) {
        float a = b2[t];
#pragma unroll 8
        for (int k = 0; k < LIN; ++k) a += z1[k] * w2[k * NCLS + t];
        lg[t] = a;
    }
    __syncthreads();
    if (t == 0) {
        float m = lg[0];
        for (int j = 1; j < NCLS; ++j) m = fmaxf(m, lg[j]);
        float s = 0.f;
        for (int j = 0; j < NCLS; ++j) s += expf(lg[j] - m);
        float lse = m + logf(s);
        for (int j = 0; j < NCLS; ++j) {
            long o = (long)g * NCLS + j;
            if (o < out_n) out[o] = lg[j] - lse;
        }
    }
}

// ---------------- launch ----------------------------------------
extern "C" void kernel_launch(void* const* d_in, const int* in_sizes, int n_in,
                              void* d_out, int out_size) {
    const float* x    = (const float*)d_in[0];
    const void*  ei   = d_in[1];
    const void*  bat  = d_in[2];
    const float* W1   = (const float*)d_in[3];
    const float* b1   = (const float*)d_in[4];
    const float* W2   = (const float*)d_in[5];
    const float* b2   = (const float*)d_in[6];
    const float* W3   = (const float*)d_in[7];
    const float* b3   = (const float*)d_in[8];
    const float* l1w  = (const float*)d_in[9];
    const float* l1b  = (const float*)d_in[10];
    const float* l2w  = (const float*)d_in[11];
    const float* l2b  = (const float*)d_in[12];
    float* out = (float*)d_out;

    const int  M = in_sizes[0] / C;          // 50000 nodes
    const long E = (long)in_sizes[1] / 2;    // 1.6M edges
    const int  N = in_sizes[2];              // == M

    float *H, *A1, *A2;
    cudaGetSymbolAddress((void**)&H,  g_H);
    cudaGetSymbolAddress((void**)&A1, g_A1);
    cudaGetSymbolAddress((void**)&A2, g_A2);

    // ---- preprocessing ----
    k_init<<<256, 256>>>(out, (long)out_size);
    k_detect<<<1024, 256>>>((const unsigned*)ei, (long)in_sizes[1],
                            (const unsigned*)bat, (long)in_sizes[2]);
    k_deg<<<(int)((E + 255) / 256), 256>>>(ei, E);
    k_dinv<<<(M + 255) / 256, 256>>>(M);
    k_scan<<<1, 1024>>>(M);
    k_fill<<<(int)((E + 255) / 256), 256>>>(ei, E);

    const int gemm_blocks   = (M + 31) / 32;
    const int gather_blocks = (M + 7) / 8;    // 8 warps per 256-thread block

    // ---- 3 GCN layers: GEMM then gather-aggregate(+bias+relu) ----
    k_gemm  <<<gemm_blocks, 256>>>(x, W1, H, M);
    k_gather<<<gather_blocks, 256>>>(H, A1, b1, M);

    k_gemm  <<<gemm_blocks, 256>>>(A1, W2, H, M);
    k_gather<<<gather_blocks, 256>>>(H, A2, b2, M);

    k_gemm  <<<gemm_blocks, 256>>>(A2, W3, H, M);
    k_gather<<<gather_blocks, 256>>>(H, A1, b3, M);

    // ---- pool + MLP ----
    k_pool<<<NGRAPH, C>>>(A1, bat, N);
    k_mlp<<<NGRAPH, LIN>>>(l1w, l1b, l2w, l2b, out, (long)out_size);
}